// round 16
// baseline (speedup 1.0000x reference)
#include <cuda_runtime.h>
#include <cuda_fp16.h>
#include <math.h>
#include <stdint.h>

#define B_   2
#define S_   2048
#define HID_ 2048
#define NH_  32
#define G_   4
#define HD_  64
#define HKV_ 8
#define NQK_ 512   // HKV_*HD_
#define M_   (B_ * S_)   // 4096

// fp16 post-rope / projected tensors
__device__ uint4 g_Qh[(size_t)M_*NQK_/8];
__device__ uint4 g_Kh[(size_t)M_*NQK_/8];
__device__ uint4 g_Vh[(size_t)M_*HID_/8];
// fp16 pre-converted GEMM operands
__device__ uint2 g_Xh[(size_t)M_*HID_/4];
__device__ uint2 g_Wqh[(size_t)HID_*NQK_/4];
__device__ uint2 g_Wkh[(size_t)HID_*NQK_/4];
__device__ uint2 g_Wvh[(size_t)HID_*HID_/4];

// ===========================================================================
// helpers
// ===========================================================================
__device__ __forceinline__ uint32_t smem_to_u32(const void* smem_ptr) {
    uint32_t addr;
    asm("{ .reg .u64 tmp; cvta.to.shared.u64 tmp, %1; cvt.u32.u64 %0, tmp; }"
        : "=r"(addr) : "l"(smem_ptr));
    return addr;
}
__device__ __forceinline__ uint32_t pack_hf2(float a, float b) {
    uint32_t r;
    asm("cvt.rn.f16x2.f32 %0, %1, %2;" : "=r"(r) : "f"(b), "f"(a));
    return r;
}
__device__ __forceinline__ void ldmx4(uint32_t r[4], uint32_t addr) {
    asm volatile("ldmatrix.sync.aligned.m8n8.x4.shared.b16 {%0,%1,%2,%3}, [%4];"
        : "=r"(r[0]), "=r"(r[1]), "=r"(r[2]), "=r"(r[3]) : "r"(addr));
}
__device__ __forceinline__ void ldmx4t(uint32_t r[4], uint32_t addr) {
    asm volatile("ldmatrix.sync.aligned.m8n8.x4.trans.shared.b16 {%0,%1,%2,%3}, [%4];"
        : "=r"(r[0]), "=r"(r[1]), "=r"(r[2]), "=r"(r[3]) : "r"(addr));
}
__device__ __forceinline__ void mma16816h(float d[4], const uint32_t a[4],
                                          const uint32_t b[2]) {
    asm volatile(
        "mma.sync.aligned.m16n8k16.row.col.f32.f16.f16.f32 "
        "{%0,%1,%2,%3}, {%4,%5,%6,%7}, {%8,%9}, {%0,%1,%2,%3};"
        : "+f"(d[0]), "+f"(d[1]), "+f"(d[2]), "+f"(d[3])
        : "r"(a[0]), "r"(a[1]), "r"(a[2]), "r"(a[3]), "r"(b[0]), "r"(b[1]));
}
__device__ __forceinline__ void cp16(uint32_t dst, const void* src) {
    asm volatile("cp.async.cg.shared.global [%0], [%1], 16;"
                 :: "r"(dst), "l"(src));
}
__device__ __forceinline__ void cp_commit() {
    asm volatile("cp.async.commit_group;" ::: "memory");
}
template <int N>
__device__ __forceinline__ void cp_wait() {
    asm volatile("cp.async.wait_group %0;" :: "n"(N) : "memory");
}

// ===========================================================================
// Fused pre-convert fp32 -> fp16 (X, Wq, Wk, Wv in one launch, 4 f4/thread)
// ===========================================================================
__global__ __launch_bounds__(256)
void cvt_all_kernel(const float4* __restrict__ X,
                    const float4* __restrict__ Wq,
                    const float4* __restrict__ Wk,
                    const float4* __restrict__ Wv,
                    uint2* __restrict__ xh, uint2* __restrict__ wqh,
                    uint2* __restrict__ wkh, uint2* __restrict__ wvh) {
    const float4* src;
    uint2* dst;
    int n4;
    switch (blockIdx.y) {
        case 0: src = X;  dst = xh;  n4 = M_ * HID_ / 4;   break;
        case 1: src = Wq; dst = wqh; n4 = HID_ * NQK_ / 4; break;
        case 2: src = Wk; dst = wkh; n4 = HID_ * NQK_ / 4; break;
        default: src = Wv; dst = wvh; n4 = HID_ * HID_ / 4; break;
    }
    int i = (blockIdx.x * blockDim.x + threadIdx.x) * 4;
    if (i >= n4) return;
    #pragma unroll
    for (int j = 0; j < 4; j++) {
        float4 v = src[i + j];
        dst[i + j] = make_uint2(pack_hf2(v.x, v.y), pack_hf2(v.z, v.w));
    }
}

// ===========================================================================
// Fused 1-term fp16 GEMM, CTA tile 128x128, warp 32x64 (4m x 2n), occ 2.
// (unchanged from R15)
// ===========================================================================
#define SAe 40
#define SBe2 136
#define ST_AHI 0
#define ST_BHI 10240
#define ST_SZ  18944
#define NSTG 4
#define GEMM_SMEM (NSTG * ST_SZ)   // 75776

__global__ __launch_bounds__(256, 2)
void gemm_fused_kernel(const char* __restrict__ Ah,
                       const char* __restrict__ BhQ, __half* __restrict__ CQ,
                       const char* __restrict__ BhK, __half* __restrict__ CK,
                       const char* __restrict__ BhV, __half* __restrict__ CV,
                       const int* __restrict__ pid) {
    extern __shared__ char sm[];
    const uint32_t smb = smem_to_u32(sm);
    const int tid = threadIdx.x, lane = tid & 31, wid = tid >> 5;
    const int wm = wid >> 1, wn = wid & 1;
    const int m0 = blockIdx.y * 128;
    const int nb = blockIdx.x;

    const char* Bh;
    __half* C;
    int N, n0;
    if (nb < 4)       { Bh = BhQ; C = CQ; N = NQK_; n0 = nb * 128; }
    else if (nb < 8)  { Bh = BhK; C = CK; N = NQK_; n0 = (nb - 4) * 128; }
    else              { Bh = BhV; C = CV; N = HID_; n0 = (nb - 8) * 128; }
    const int K = HID_;

    float acc[2][8][4];
    #pragma unroll
    for (int i = 0; i < 2; i++)
        #pragma unroll
        for (int j = 0; j < 8; j++)
            #pragma unroll
            for (int t = 0; t < 4; t++) acc[i][j][t] = 0.f;

    const uint32_t aRow  = lane & 15;
    const uint32_t aColH = (lane >> 4) * 8;
    const uint32_t bRow  = (lane & 7) + ((lane >> 3) & 1) * 8;
    const uint32_t bCol  = ((lane >> 4) & 1) * 8;
    const int nch = K >> 5;

    auto issue = [&](int s, int k0) {
        uint32_t sb = smb + s * ST_SZ;
        #pragma unroll
        for (int i = 0; i < 2; i++) {
            int idx = tid + (i << 8);
            int row = idx >> 2, seg = idx & 3;
            size_t go = ((size_t)(m0 + row) * K + k0 + seg * 8) * 2;
            cp16(sb + ST_AHI + row * 80 + seg * 16, Ah + go);
        }
        #pragma unroll
        for (int i = 0; i < 2; i++) {
            int idx = tid + (i << 8);
            int row = idx >> 4, seg = idx & 15;
            size_t go = ((size_t)(k0 + row) * N + n0 + seg * 8) * 2;
            cp16(sb + ST_BHI + row * 272 + seg * 16, Bh + go);
        }
        cp_commit();
    };

    issue(0, 0);
    issue(1, 32);
    for (int c = 0; c < nch; c++) {
        if (c + 2 < nch) issue((c + 2) & (NSTG - 1), (c + 2) << 5);
        else             cp_commit();
        cp_wait<2>();
        __syncthreads();

        const uint32_t sb = smb + (c & (NSTG - 1)) * ST_SZ;
        #pragma unroll
        for (int ks = 0; ks < 2; ks++) {
            uint32_t aH[2][4];
            #pragma unroll
            for (int mf = 0; mf < 2; mf++) {
                uint32_t ao = ((wm * 32 + mf * 16 + aRow) * SAe + ks * 16 + aColH) * 2;
                ldmx4(aH[mf], sb + ST_AHI + ao);
            }
            uint32_t bH[4][4];
            #pragma unroll
            for (int ng = 0; ng < 4; ng++) {
                uint32_t bo = ((ks * 16 + bRow) * SBe2 + wn * 64 + ng * 16 + bCol) * 2;
                ldmx4t(bH[ng], sb + ST_BHI + bo);
            }
            #pragma unroll
            for (int mf = 0; mf < 2; mf++)
                #pragma unroll
                for (int ng = 0; ng < 4; ng++) {
                    mma16816h(acc[mf][ng*2+0], aH[mf], bH[ng]);
                    mma16816h(acc[mf][ng*2+1], aH[mf], bH[ng] + 2);
                }
        }
    }

    if (nb >= 8) {
        #pragma unroll
        for (int mf = 0; mf < 2; mf++) {
            int row = m0 + wm * 32 + mf * 16 + (lane >> 2);
            #pragma unroll
            for (int nf = 0; nf < 8; nf++) {
                int col = n0 + wn * 64 + nf * 8 + (lane & 3) * 2;
                *reinterpret_cast<uint32_t*>(C + (size_t)row * N + col) =
                    pack_hf2(acc[mf][nf][0], acc[mf][nf][1]);
                *reinterpret_cast<uint32_t*>(C + (size_t)(row + 8) * N + col) =
                    pack_hf2(acc[mf][nf][2], acc[mf][nf][3]);
            }
        }
    } else {
        const float qscale = (nb < 4) ? 0.125f : 1.0f;
        float inv0[4], inv1[4];
        #pragma unroll
        for (int nf = 0; nf < 4; nf++) {
            int d = nf * 8 + (lane & 3) * 2;
            inv0[nf] = powf(10000.0f, -(float)d       * (1.0f / 32.0f));
            inv1[nf] = powf(10000.0f, -(float)(d + 1) * (1.0f / 32.0f));
        }
        #pragma unroll
        for (int mf = 0; mf < 2; mf++) {
            int row = m0 + wm * 32 + mf * 16 + (lane >> 2);
            float pos0 = (float)pid[row];
            float pos1 = (float)pid[row + 8];
            #pragma unroll
            for (int nf = 0; nf < 4; nf++) {
                int col = n0 + wn * 64 + nf * 8 + (lane & 3) * 2;
                float s00, c00, s01, c01, s10, c10, s11, c11;
                sincosf(pos0 * inv0[nf], &s00, &c00);
                sincosf(pos0 * inv1[nf], &s01, &c01);
                sincosf(pos1 * inv0[nf], &s10, &c10);
                sincosf(pos1 * inv1[nf], &s11, &c11);
                float x0a = acc[mf][nf][0],   x0b = acc[mf][nf][1];
                float x1a = acc[mf][nf][2],   x1b = acc[mf][nf][3];
                float y0a = acc[mf][nf+4][0], y0b = acc[mf][nf+4][1];
                float y1a = acc[mf][nf+4][2], y1b = acc[mf][nf+4][3];
                float r0a = (x0a * c00 - y0a * s00) * qscale;
                float r0b = (x0b * c01 - y0b * s01) * qscale;
                float u0a = (y0a * c00 + x0a * s00) * qscale;
                float u0b = (y0b * c01 + x0b * s01) * qscale;
                float r1a = (x1a * c10 - y1a * s10) * qscale;
                float r1b = (x1b * c11 - y1b * s11) * qscale;
                float u1a = (y1a * c10 + x1a * s10) * qscale;
                float u1b = (y1b * c11 + x1b * s11) * qscale;
                __half* Cr0 = C + (size_t)row * N;
                __half* Cr1 = C + (size_t)(row + 8) * N;
                *reinterpret_cast<uint32_t*>(Cr0 + col)      = pack_hf2(r0a, r0b);
                *reinterpret_cast<uint32_t*>(Cr0 + col + 32) = pack_hf2(u0a, u0b);
                *reinterpret_cast<uint32_t*>(Cr1 + col)      = pack_hf2(r1a, r1b);
                *reinterpret_cast<uint32_t*>(Cr1 + col + 32) = pack_hf2(u1a, u1b);
            }
        }
    }
}

// ===========================================================================
// FA2-style flash attention, warp = 32 rows x 128 cols (4 rowgroups x 2 col-
// groups): halves per-tile V smem traffic. Paired qt scheduling, cp.async
// double buffer. 1-term QK + 1-term PV. smem ~102 KB, 1 CTA/SM.
// ===========================================================================
#define SK   72
#define SV   264
#define QHI_O 0
#define KST_SZ 9216
#define VST_SZ 33792
#define KHI_O 18432
#define VHI_O (18432 + 2 * KST_SZ)               // 36864
#define ATTN_SMEM (VHI_O + 2 * VST_SZ)           // 104448
#define QT_ROWS 128
#define NQT (S_ / QT_ROWS)                       // 16

__global__ __launch_bounds__(256, 1)
void attn_mma_kernel(const uint4* __restrict__ Qh,
                     const uint4* __restrict__ Kh, const uint4* __restrict__ Vh,
                     float* __restrict__ Out) {
    extern __shared__ char sm[];
    const uint32_t smb = smem_to_u32(sm);
    const int tid = threadIdx.x, lane = tid & 31, wid = tid >> 5;
    const int b  = blockIdx.z;
    const int h  = blockIdx.y;
    const int bx = blockIdx.x;   // 0..7
    const int wr = wid >> 1;     // rowgroup 0..3 (32 rows each)
    const int wc = wid & 1;      // colgroup 0..1 (128 cols each)

    const int r0l = lane >> 2;
    const int cql = (lane & 3) * 2;
    const uint32_t aRow  = lane & 15;
    const uint32_t aColH = (lane >> 4) * 8;
    const uint32_t kbRow = (lane & 7) + ((lane >> 4) & 1) * 8;
    const uint32_t kbCol = ((lane >> 3) & 1) * 8;
    const uint32_t vbRow = (lane & 7) + ((lane >> 3) & 1) * 8;
    const uint32_t vbCol = ((lane >> 4) & 1) * 8;

    for (int half = 0; half < 2; half++) {
        const int qt = half ? bx : (NQT - 1 - bx);
        const int q0 = qt * QT_ROWS;
        const int nkt = 2 * qt + 2;

        __syncthreads();   // prior half fully done with all smem

        #pragma unroll
        for (int i = 0; i < 4; i++) {
            int idx = tid + (i << 8);
            int r = idx >> 3, c8 = idx & 7;
            size_t gi = (size_t)(b * S_ + q0 + r) * 64 + h * 8 + c8;
            *reinterpret_cast<uint4*>(sm + QHI_O + (r * SK + c8 * 8) * 2) = Qh[gi];
        }

        float acc[2][16][4];
        #pragma unroll
        for (int mf = 0; mf < 2; mf++)
            #pragma unroll
            for (int i = 0; i < 16; i++)
                #pragma unroll
                for (int t = 0; t < 4; t++) acc[mf][i][t] = 0.f;
        float mrow[2][2], lrow[2][2];
        #pragma unroll
        for (int mf = 0; mf < 2; mf++) {
            mrow[mf][0] = -INFINITY; mrow[mf][1] = -INFINITY;
            lrow[mf][0] = 0.f;       lrow[mf][1] = 0.f;
        }

        const int rowb = wr * 32;
        const int rmaxw = q0 + rowb + 31;

        auto issueKV = [&](int kt) {
            const int s  = kt & 1;
            const int k0 = kt * 64;
            const uint32_t kb = smb + KHI_O + s * KST_SZ;
            const uint32_t vb = smb + VHI_O + s * VST_SZ;
            #pragma unroll
            for (int i = 0; i < 2; i++) {
                int idx = tid + (i << 8);
                int kk = idx >> 3, c8 = idx & 7;
                size_t gi = (size_t)(b * S_ + k0 + kk) * 64 + h * 8 + c8;
                cp16(kb + (kk * SK + c8 * 8) * 2, Kh + gi);
            }
            #pragma unroll
            for (int i = 0; i < 8; i++) {
                int idx = tid + (i << 8);
                int kk = idx >> 5, c8 = idx & 31;
                int g = c8 >> 3, d8 = c8 & 7;
                size_t gi = (size_t)(b * S_ + k0 + kk) * 256 + g * 64 + h * 8 + d8;
                cp16(vb + (kk * SV + c8 * 8) * 2, Vh + gi);
            }
            cp_commit();
        };

        issueKV(0);
        for (int kt = 0; kt < nkt; kt++) {
            const int k0 = kt * 64;
            __syncthreads();
            if (kt + 1 < nkt) issueKV(kt + 1);
            else              cp_commit();
            cp_wait<1>();
            __syncthreads();

            if (k0 > rmaxw) continue;

            const uint32_t kb = smb + KHI_O + (kt & 1) * KST_SZ;
            const uint32_t vb = smb + VHI_O + (kt & 1) * VST_SZ;

            // ---- QK^T: S(32x64) in registers (2 mfrags share each bH) ----
            float sfr[2][8][4];
            #pragma unroll
            for (int mf = 0; mf < 2; mf++)
                #pragma unroll
                for (int i = 0; i < 8; i++)
                    #pragma unroll
                    for (int t = 0; t < 4; t++) sfr[mf][i][t] = 0.f;

            #pragma unroll
            for (int ks = 0; ks < 4; ks++) {
                uint32_t aH0[4], aH1[4];
                uint32_t ao0 = ((rowb + aRow) * SK + ks * 16 + aColH) * 2;
                uint32_t ao1 = ((rowb + 16 + aRow) * SK + ks * 16 + aColH) * 2;
                ldmx4(aH0, smb + QHI_O + ao0);
                ldmx4(aH1, smb + QHI_O + ao1);
                #pragma unroll
                for (int g4 = 0; g4 < 4; g4++) {
                    uint32_t bH[4];
                    uint32_t bo = ((g4 * 16 + kbRow) * SK + ks * 16 + kbCol) * 2;
                    ldmx4(bH, kb + bo);
                    mma16816h(sfr[0][g4*2+0], aH0, bH);
                    mma16816h(sfr[0][g4*2+1], aH0, bH + 2);
                    mma16816h(sfr[1][g4*2+0], aH1, bH);
                    mma16816h(sfr[1][g4*2+1], aH1, bH + 2);
                }
            }

            // ---- per-mfrag mask + softmax + pack + rescale ----
            uint32_t pa[2][4][4];
            #pragma unroll
            for (int mf = 0; mf < 2; mf++) {
                const int rminm = q0 + rowb + mf * 16;
                if (k0 + 63 > rminm) {
                    int grow0 = rminm + r0l, grow1 = grow0 + 8;
                    #pragma unroll
                    for (int nf = 0; nf < 8; nf++) {
                        int c = k0 + nf * 8 + cql;
                        if (c     > grow0) sfr[mf][nf][0] = -INFINITY;
                        if (c + 1 > grow0) sfr[mf][nf][1] = -INFINITY;
                        if (c     > grow1) sfr[mf][nf][2] = -INFINITY;
                        if (c + 1 > grow1) sfr[mf][nf][3] = -INFINITY;
                    }
                }

                float mx0 = -INFINITY, mx1 = -INFINITY;
                #pragma unroll
                for (int nf = 0; nf < 8; nf++) {
                    mx0 = fmaxf(mx0, fmaxf(sfr[mf][nf][0], sfr[mf][nf][1]));
                    mx1 = fmaxf(mx1, fmaxf(sfr[mf][nf][2], sfr[mf][nf][3]));
                }
                mx0 = fmaxf(mx0, __shfl_xor_sync(0xffffffffu, mx0, 1));
                mx0 = fmaxf(mx0, __shfl_xor_sync(0xffffffffu, mx0, 2));
                mx1 = fmaxf(mx1, __shfl_xor_sync(0xffffffffu, mx1, 1));
                mx1 = fmaxf(mx1, __shfl_xor_sync(0xffffffffu, mx1, 2));
                float mn0 = fmaxf(mrow[mf][0], mx0);
                float mn1 = fmaxf(mrow[mf][1], mx1);
                float sc0 = __expf(mrow[mf][0] - mn0);
                float sc1 = __expf(mrow[mf][1] - mn1);

                float sum0 = 0.f, sum1 = 0.f;
                #pragma unroll
                for (int nf = 0; nf < 8; nf++) {
                    float p0 = __expf(sfr[mf][nf][0] - mn0);
                    float p1 = __expf(sfr[mf][nf][1] - mn0);
                    float p2 = __expf(sfr[mf][nf][2] - mn1);
                    float p3 = __expf(sfr[mf][nf][3] - mn1);
                    sum0 += p0 + p1;
                    sum1 += p2 + p3;
                    pa[mf][nf >> 1][(nf & 1) * 2 + 0] = pack_hf2(p0, p1);
                    pa[mf][nf >> 1][(nf & 1) * 2 + 1] = pack_hf2(p2, p3);
                }
                sum0 += __shfl_xor_sync(0xffffffffu, sum0, 1);
                sum0 += __shfl_xor_sync(0xffffffffu, sum0, 2);
                sum1 += __shfl_xor_sync(0xffffffffu, sum1, 1);
                sum1 += __shfl_xor_sync(0xffffffffu, sum1, 2);
                lrow[mf][0] = lrow[mf][0] * sc0 + sum0;
                lrow[mf][1] = lrow[mf][1] * sc1 + sum1;
                mrow[mf][0] = mn0; mrow[mf][1] = mn1;

                #pragma unroll
                for (int i = 0; i < 16; i++) {
                    acc[mf][i][0] *= sc0; acc[mf][i][1] *= sc0;
                    acc[mf][i][2] *= sc1; acc[mf][i][3] *= sc1;
                }
            }

            // ---- PV: both mfrags share each vH ----
            #pragma unroll
            for (int ks = 0; ks < 4; ks++) {
                #pragma unroll
                for (int g = 0; g < 8; g++) {
                    uint32_t vH[4];
                    uint32_t bo = ((ks * 16 + vbRow) * SV + wc * 128 + g * 16 + vbCol) * 2;
                    ldmx4t(vH, vb + bo);
                    mma16816h(acc[0][g*2+0], pa[0][ks], vH);
                    mma16816h(acc[0][g*2+1], pa[0][ks], vH + 2);
                    mma16816h(acc[1][g*2+0], pa[1][ks], vH);
                    mma16816h(acc[1][g*2+1], pa[1][ks], vH + 2);
                }
            }
        }

        // ---- normalize + store ----
        #pragma unroll
        for (int mf = 0; mf < 2; mf++) {
            float invl0 = 1.f / lrow[mf][0];
            float invl1 = 1.f / lrow[mf][1];
            int row0 = q0 + rowb + mf * 16 + r0l;
            int row1 = row0 + 8;
            #pragma unroll
            for (int nf = 0; nf < 16; nf++) {
                int cl = wc * 128 + nf * 8 + cql;
                int g  = cl >> 6, d = cl & 63;
                size_t ob0 = ((size_t)(b * S_ + row0)) * HID_ + (g * HKV_ + h) * HD_ + d;
                size_t ob1 = ((size_t)(b * S_ + row1)) * HID_ + (g * HKV_ + h) * HD_ + d;
                *reinterpret_cast<float2*>(&Out[ob0]) =
                    make_float2(acc[mf][nf][0] * invl0, acc[mf][nf][1] * invl0);
                *reinterpret_cast<float2*>(&Out[ob1]) =
                    make_float2(acc[mf][nf][2] * invl1, acc[mf][nf][3] * invl1);
            }
        }
    }
}

// ---------------------------------------------------------------------------
extern "C" void kernel_launch(void* const* d_in, const int* in_sizes, int n_in,
                              void* d_out, int out_size) {
    const float* X   = (const float*)d_in[0];
    const int*   pid = (const int*)  d_in[1];
    const float* Wq  = (const float*)d_in[2];
    const float* Wk  = (const float*)d_in[3];
    const float* Wv  = (const float*)d_in[4];
    float* Out = (float*)d_out;

    uint4 *qh, *kh, *vh;
    cudaGetSymbolAddress((void**)&qh, g_Qh);
    cudaGetSymbolAddress((void**)&kh, g_Kh);
    cudaGetSymbolAddress((void**)&vh, g_Vh);
    uint2 *xh, *wqh, *wkh, *wvh;
    cudaGetSymbolAddress((void**)&xh,  g_Xh);
    cudaGetSymbolAddress((void**)&wqh, g_Wqh);
    cudaGetSymbolAddress((void**)&wkh, g_Wkh);
    cudaGetSymbolAddress((void**)&wvh, g_Wvh);

    // Fused pre-convert (4 float4 per thread)
    {
        int nX4 = M_ * HID_ / 4;
        dim3 grd((nX4 / 4 + 255) / 256, 4);
        cvt_all_kernel<<<grd, 256>>>((const float4*)X, (const float4*)Wq,
                                     (const float4*)Wk, (const float4*)Wv,
                                     xh, wqh, wkh, wvh);
    }
    // Fused projections + in-epilogue RoPE, CTA 128x128 occ-2
    {
        cudaFuncSetAttribute(gemm_fused_kernel,
                             cudaFuncAttributeMaxDynamicSharedMemorySize, GEMM_SMEM);
        dim3 grd(24, M_ / 128);
        gemm_fused_kernel<<<grd, 256, GEMM_SMEM>>>(
            (const char*)xh, (const char*)wqh, (__half*)qh,
            (const char*)wkh, (__half*)kh, (const char*)wvh, (__half*)vh, pid);
    }
    // Attention (FA2-style, 4x2 warp partition, paired scheduling)
    {
        cudaFuncSetAttribute(attn_mma_kernel,
                             cudaFuncAttributeMaxDynamicSharedMemorySize, ATTN_SMEM);
        dim3 grd(NQT / 2, HKV_, B_);
        attn_mma_kernel<<<grd, 256, ATTN_SMEM>>>(qh, kh, vh, Out);
    }
}

// round 17
// speedup vs baseline: 1.1014x; 1.1014x over previous
#include <cuda_runtime.h>
#include <cuda_fp16.h>
#include <math.h>
#include <stdint.h>

#define B_   2
#define S_   2048
#define HID_ 2048
#define NH_  32
#define G_   4
#define HD_  64
#define HKV_ 8
#define NQK_ 512   // HKV_*HD_
#define M_   (B_ * S_)   // 4096

// fp16 post-rope / projected tensors
__device__ uint4 g_Qh[(size_t)M_*NQK_/8];
__device__ uint4 g_Kh[(size_t)M_*NQK_/8];
__device__ uint4 g_Vh[(size_t)M_*HID_/8];
// fp16 pre-converted GEMM operands
__device__ uint2 g_Xh[(size_t)M_*HID_/4];
__device__ uint2 g_Wqh[(size_t)HID_*NQK_/4];
__device__ uint2 g_Wkh[(size_t)HID_*NQK_/4];
__device__ uint2 g_Wvh[(size_t)HID_*HID_/4];

// ===========================================================================
// helpers
// ===========================================================================
__device__ __forceinline__ uint32_t smem_to_u32(const void* smem_ptr) {
    uint32_t addr;
    asm("{ .reg .u64 tmp; cvta.to.shared.u64 tmp, %1; cvt.u32.u64 %0, tmp; }"
        : "=r"(addr) : "l"(smem_ptr));
    return addr;
}
__device__ __forceinline__ uint32_t pack_hf2(float a, float b) {
    uint32_t r;
    asm("cvt.rn.f16x2.f32 %0, %1, %2;" : "=r"(r) : "f"(b), "f"(a));
    return r;
}
__device__ __forceinline__ void ldmx4(uint32_t r[4], uint32_t addr) {
    asm volatile("ldmatrix.sync.aligned.m8n8.x4.shared.b16 {%0,%1,%2,%3}, [%4];"
        : "=r"(r[0]), "=r"(r[1]), "=r"(r[2]), "=r"(r[3]) : "r"(addr));
}
__device__ __forceinline__ void ldmx4t(uint32_t r[4], uint32_t addr) {
    asm volatile("ldmatrix.sync.aligned.m8n8.x4.trans.shared.b16 {%0,%1,%2,%3}, [%4];"
        : "=r"(r[0]), "=r"(r[1]), "=r"(r[2]), "=r"(r[3]) : "r"(addr));
}
__device__ __forceinline__ void mma16816h(float d[4], const uint32_t a[4],
                                          const uint32_t b[2]) {
    asm volatile(
        "mma.sync.aligned.m16n8k16.row.col.f32.f16.f16.f32 "
        "{%0,%1,%2,%3}, {%4,%5,%6,%7}, {%8,%9}, {%0,%1,%2,%3};"
        : "+f"(d[0]), "+f"(d[1]), "+f"(d[2]), "+f"(d[3])
        : "r"(a[0]), "r"(a[1]), "r"(a[2]), "r"(a[3]), "r"(b[0]), "r"(b[1]));
}
__device__ __forceinline__ void cp16(uint32_t dst, const void* src) {
    asm volatile("cp.async.cg.shared.global [%0], [%1], 16;"
                 :: "r"(dst), "l"(src));
}
__device__ __forceinline__ void cp_commit() {
    asm volatile("cp.async.commit_group;" ::: "memory");
}
template <int N>
__device__ __forceinline__ void cp_wait() {
    asm volatile("cp.async.wait_group %0;" :: "n"(N) : "memory");
}

// ===========================================================================
// Fused pre-convert fp32 -> fp16 (X, Wq, Wk, Wv in one launch, 2 f4/thread)
// ===========================================================================
__global__ __launch_bounds__(256)
void cvt_all_kernel(const float4* __restrict__ X,
                    const float4* __restrict__ Wq,
                    const float4* __restrict__ Wk,
                    const float4* __restrict__ Wv,
                    uint2* __restrict__ xh, uint2* __restrict__ wqh,
                    uint2* __restrict__ wkh, uint2* __restrict__ wvh) {
    const float4* src;
    uint2* dst;
    int n4;
    switch (blockIdx.y) {
        case 0: src = X;  dst = xh;  n4 = M_ * HID_ / 4;   break;
        case 1: src = Wq; dst = wqh; n4 = HID_ * NQK_ / 4; break;
        case 2: src = Wk; dst = wkh; n4 = HID_ * NQK_ / 4; break;
        default: src = Wv; dst = wvh; n4 = HID_ * HID_ / 4; break;
    }
    int i = (blockIdx.x * blockDim.x + threadIdx.x) * 2;
    if (i >= n4) return;
    float4 v0 = src[i];
    float4 v1 = src[i + 1];
    dst[i]     = make_uint2(pack_hf2(v0.x, v0.y), pack_hf2(v0.z, v0.w));
    dst[i + 1] = make_uint2(pack_hf2(v1.x, v1.y), pack_hf2(v1.z, v1.w));
}

// ===========================================================================
// Fused 1-term fp16 GEMM, CTA tile 128x128, warp 32x64 (4m x 2n), occ 2.
// (unchanged from R15)
// ===========================================================================
#define SAe 40
#define SBe2 136
#define ST_AHI 0
#define ST_BHI 10240
#define ST_SZ  18944
#define NSTG 4
#define GEMM_SMEM (NSTG * ST_SZ)   // 75776

__global__ __launch_bounds__(256, 2)
void gemm_fused_kernel(const char* __restrict__ Ah,
                       const char* __restrict__ BhQ, __half* __restrict__ CQ,
                       const char* __restrict__ BhK, __half* __restrict__ CK,
                       const char* __restrict__ BhV, __half* __restrict__ CV,
                       const int* __restrict__ pid) {
    extern __shared__ char sm[];
    const uint32_t smb = smem_to_u32(sm);
    const int tid = threadIdx.x, lane = tid & 31, wid = tid >> 5;
    const int wm = wid >> 1, wn = wid & 1;
    const int m0 = blockIdx.y * 128;
    const int nb = blockIdx.x;

    const char* Bh;
    __half* C;
    int N, n0;
    if (nb < 4)       { Bh = BhQ; C = CQ; N = NQK_; n0 = nb * 128; }
    else if (nb < 8)  { Bh = BhK; C = CK; N = NQK_; n0 = (nb - 4) * 128; }
    else              { Bh = BhV; C = CV; N = HID_; n0 = (nb - 8) * 128; }
    const int K = HID_;

    float acc[2][8][4];
    #pragma unroll
    for (int i = 0; i < 2; i++)
        #pragma unroll
        for (int j = 0; j < 8; j++)
            #pragma unroll
            for (int t = 0; t < 4; t++) acc[i][j][t] = 0.f;

    const uint32_t aRow  = lane & 15;
    const uint32_t aColH = (lane >> 4) * 8;
    const uint32_t bRow  = (lane & 7) + ((lane >> 3) & 1) * 8;
    const uint32_t bCol  = ((lane >> 4) & 1) * 8;
    const int nch = K >> 5;

    auto issue = [&](int s, int k0) {
        uint32_t sb = smb + s * ST_SZ;
        #pragma unroll
        for (int i = 0; i < 2; i++) {
            int idx = tid + (i << 8);
            int row = idx >> 2, seg = idx & 3;
            size_t go = ((size_t)(m0 + row) * K + k0 + seg * 8) * 2;
            cp16(sb + ST_AHI + row * 80 + seg * 16, Ah + go);
        }
        #pragma unroll
        for (int i = 0; i < 2; i++) {
            int idx = tid + (i << 8);
            int row = idx >> 4, seg = idx & 15;
            size_t go = ((size_t)(k0 + row) * N + n0 + seg * 8) * 2;
            cp16(sb + ST_BHI + row * 272 + seg * 16, Bh + go);
        }
        cp_commit();
    };

    issue(0, 0);
    issue(1, 32);
    for (int c = 0; c < nch; c++) {
        if (c + 2 < nch) issue((c + 2) & (NSTG - 1), (c + 2) << 5);
        else             cp_commit();
        cp_wait<2>();
        __syncthreads();

        const uint32_t sb = smb + (c & (NSTG - 1)) * ST_SZ;
        #pragma unroll
        for (int ks = 0; ks < 2; ks++) {
            uint32_t aH[2][4];
            #pragma unroll
            for (int mf = 0; mf < 2; mf++) {
                uint32_t ao = ((wm * 32 + mf * 16 + aRow) * SAe + ks * 16 + aColH) * 2;
                ldmx4(aH[mf], sb + ST_AHI + ao);
            }
            uint32_t bH[4][4];
            #pragma unroll
            for (int ng = 0; ng < 4; ng++) {
                uint32_t bo = ((ks * 16 + bRow) * SBe2 + wn * 64 + ng * 16 + bCol) * 2;
                ldmx4t(bH[ng], sb + ST_BHI + bo);
            }
            #pragma unroll
            for (int mf = 0; mf < 2; mf++)
                #pragma unroll
                for (int ng = 0; ng < 4; ng++) {
                    mma16816h(acc[mf][ng*2+0], aH[mf], bH[ng]);
                    mma16816h(acc[mf][ng*2+1], aH[mf], bH[ng] + 2);
                }
        }
    }

    if (nb >= 8) {
        #pragma unroll
        for (int mf = 0; mf < 2; mf++) {
            int row = m0 + wm * 32 + mf * 16 + (lane >> 2);
            #pragma unroll
            for (int nf = 0; nf < 8; nf++) {
                int col = n0 + wn * 64 + nf * 8 + (lane & 3) * 2;
                *reinterpret_cast<uint32_t*>(C + (size_t)row * N + col) =
                    pack_hf2(acc[mf][nf][0], acc[mf][nf][1]);
                *reinterpret_cast<uint32_t*>(C + (size_t)(row + 8) * N + col) =
                    pack_hf2(acc[mf][nf][2], acc[mf][nf][3]);
            }
        }
    } else {
        const float qscale = (nb < 4) ? 0.125f : 1.0f;
        float inv0[4], inv1[4];
        #pragma unroll
        for (int nf = 0; nf < 4; nf++) {
            int d = nf * 8 + (lane & 3) * 2;
            inv0[nf] = powf(10000.0f, -(float)d       * (1.0f / 32.0f));
            inv1[nf] = powf(10000.0f, -(float)(d + 1) * (1.0f / 32.0f));
        }
        #pragma unroll
        for (int mf = 0; mf < 2; mf++) {
            int row = m0 + wm * 32 + mf * 16 + (lane >> 2);
            float pos0 = (float)pid[row];
            float pos1 = (float)pid[row + 8];
            #pragma unroll
            for (int nf = 0; nf < 4; nf++) {
                int col = n0 + wn * 64 + nf * 8 + (lane & 3) * 2;
                float s00, c00, s01, c01, s10, c10, s11, c11;
                sincosf(pos0 * inv0[nf], &s00, &c00);
                sincosf(pos0 * inv1[nf], &s01, &c01);
                sincosf(pos1 * inv0[nf], &s10, &c10);
                sincosf(pos1 * inv1[nf], &s11, &c11);
                float x0a = acc[mf][nf][0],   x0b = acc[mf][nf][1];
                float x1a = acc[mf][nf][2],   x1b = acc[mf][nf][3];
                float y0a = acc[mf][nf+4][0], y0b = acc[mf][nf+4][1];
                float y1a = acc[mf][nf+4][2], y1b = acc[mf][nf+4][3];
                float r0a = (x0a * c00 - y0a * s00) * qscale;
                float r0b = (x0b * c01 - y0b * s01) * qscale;
                float u0a = (y0a * c00 + x0a * s00) * qscale;
                float u0b = (y0b * c01 + x0b * s01) * qscale;
                float r1a = (x1a * c10 - y1a * s10) * qscale;
                float r1b = (x1b * c11 - y1b * s11) * qscale;
                float u1a = (y1a * c10 + x1a * s10) * qscale;
                float u1b = (y1b * c11 + x1b * s11) * qscale;
                __half* Cr0 = C + (size_t)row * N;
                __half* Cr1 = C + (size_t)(row + 8) * N;
                *reinterpret_cast<uint32_t*>(Cr0 + col)      = pack_hf2(r0a, r0b);
                *reinterpret_cast<uint32_t*>(Cr0 + col + 32) = pack_hf2(u0a, u0b);
                *reinterpret_cast<uint32_t*>(Cr1 + col)      = pack_hf2(r1a, r1b);
                *reinterpret_cast<uint32_t*>(Cr1 + col + 32) = pack_hf2(u1a, u1b);
            }
        }
    }
}

// ===========================================================================
// FA2-style flash attention (R15 partition: warp = 16 rows x 256 cols),
// paired qt scheduling, 4-stage K/V ring with prefetch distance 2 and ONE
// barrier per kv-tile. 1-term QK + 1-term PV. smem ~186 KB, 1 CTA/SM.
// ===========================================================================
#define SK   72
#define SV   264
#define QHI_O 0
#define KST_SZ 9216
#define VST_SZ 33792
#define NKVS 4
#define KHI_O 18432
#define VHI_O (KHI_O + NKVS * KST_SZ)            // 55296
#define ATTN_SMEM (VHI_O + NKVS * VST_SZ)        // 190464
#define QT_ROWS 128
#define NQT (S_ / QT_ROWS)                       // 16

__global__ __launch_bounds__(256, 1)
void attn_mma_kernel(const uint4* __restrict__ Qh,
                     const uint4* __restrict__ Kh, const uint4* __restrict__ Vh,
                     float* __restrict__ Out) {
    extern __shared__ char sm[];
    const uint32_t smb = smem_to_u32(sm);
    const int tid = threadIdx.x, lane = tid & 31, wid = tid >> 5;
    const int b  = blockIdx.z;
    const int h  = blockIdx.y;
    const int bx = blockIdx.x;   // 0..7

    const int r0l = lane >> 2;
    const int cql = (lane & 3) * 2;
    const uint32_t aRow  = lane & 15;
    const uint32_t aColH = (lane >> 4) * 8;
    const uint32_t kbRow = (lane & 7) + ((lane >> 4) & 1) * 8;
    const uint32_t kbCol = ((lane >> 3) & 1) * 8;
    const uint32_t vbRow = (lane & 7) + ((lane >> 3) & 1) * 8;
    const uint32_t vbCol = ((lane >> 4) & 1) * 8;

    for (int half = 0; half < 2; half++) {
        const int qt = half ? bx : (NQT - 1 - bx);
        const int q0 = qt * QT_ROWS;
        const int nkt = 2 * qt + 2;

        __syncthreads();   // prior half fully done with all smem

        // ---- load Q tile (128 rows): 1024 uint4, 4/thread ----
        #pragma unroll
        for (int i = 0; i < 4; i++) {
            int idx = tid + (i << 8);
            int r = idx >> 3, c8 = idx & 7;
            size_t gi = (size_t)(b * S_ + q0 + r) * 64 + h * 8 + c8;
            *reinterpret_cast<uint4*>(sm + QHI_O + (r * SK + c8 * 8) * 2) = Qh[gi];
        }

        float acc[32][4];
        #pragma unroll
        for (int i = 0; i < 32; i++)
            #pragma unroll
            for (int t = 0; t < 4; t++) acc[i][t] = 0.f;
        float m0 = -INFINITY, m1 = -INFINITY, l0 = 0.f, l1 = 0.f;

        const int rmin = q0 + wid * 16;
        const int rmax = rmin + 15;

        auto issueKV = [&](int kt) {
            const int s  = kt & (NKVS - 1);
            const int k0 = kt * 64;
            const uint32_t kb = smb + KHI_O + s * KST_SZ;
            const uint32_t vb = smb + VHI_O + s * VST_SZ;
            #pragma unroll
            for (int i = 0; i < 2; i++) {
                int idx = tid + (i << 8);
                int kk = idx >> 3, c8 = idx & 7;
                size_t gi = (size_t)(b * S_ + k0 + kk) * 64 + h * 8 + c8;
                cp16(kb + (kk * SK + c8 * 8) * 2, Kh + gi);
            }
            #pragma unroll
            for (int i = 0; i < 8; i++) {
                int idx = tid + (i << 8);
                int kk = idx >> 5, c8 = idx & 31;
                int g = c8 >> 3, d8 = c8 & 7;
                size_t gi = (size_t)(b * S_ + k0 + kk) * 256 + g * 64 + h * 8 + d8;
                cp16(vb + (kk * SV + c8 * 8) * 2, Vh + gi);
            }
            cp_commit();
        };

        issueKV(0);
        if (nkt > 1) issueKV(1);
        else         cp_commit();
        for (int kt = 0; kt < nkt; kt++) {
            const int k0 = kt * 64;
            // Prefetch distance 2 into 4-deep ring: buffer (kt+2)&3 was last
            // read at iteration kt-2, guarded by the barrier of iteration kt-1.
            if (kt + 2 < nkt) issueKV(kt + 2);
            else              cp_commit();
            cp_wait<2>();      // tile kt's group complete (2 newest in flight)
            __syncthreads();   // visibility of tile kt's K/V (single barrier)

            if (k0 > rmax) continue;

            const uint32_t kb = smb + KHI_O + (kt & (NKVS - 1)) * KST_SZ;
            const uint32_t vb = smb + VHI_O + (kt & (NKVS - 1)) * VST_SZ;

            // ---- QK^T: S(16x64) in registers ----
            float sfr[8][4];
            #pragma unroll
            for (int i = 0; i < 8; i++)
                #pragma unroll
                for (int t = 0; t < 4; t++) sfr[i][t] = 0.f;

            #pragma unroll
            for (int ks = 0; ks < 4; ks++) {
                uint32_t aH[4];
                uint32_t ao = ((wid * 16 + aRow) * SK + ks * 16 + aColH) * 2;
                ldmx4(aH, smb + QHI_O + ao);
                #pragma unroll
                for (int g4 = 0; g4 < 4; g4++) {
                    uint32_t bH[4];
                    uint32_t bo = ((g4 * 16 + kbRow) * SK + ks * 16 + kbCol) * 2;
                    ldmx4(bH, kb + bo);
                    mma16816h(sfr[g4*2+0], aH, bH);
                    mma16816h(sfr[g4*2+1], aH, bH + 2);
                }
            }

            // ---- causal mask (diagonal tiles only) ----
            if (k0 + 63 > rmin) {
                int grow0 = rmin + r0l, grow1 = grow0 + 8;
                #pragma unroll
                for (int nf = 0; nf < 8; nf++) {
                    int c = k0 + nf * 8 + cql;
                    if (c     > grow0) sfr[nf][0] = -INFINITY;
                    if (c + 1 > grow0) sfr[nf][1] = -INFINITY;
                    if (c     > grow1) sfr[nf][2] = -INFINITY;
                    if (c + 1 > grow1) sfr[nf][3] = -INFINITY;
                }
            }

            // ---- in-register online softmax ----
            float mx0 = -INFINITY, mx1 = -INFINITY;
            #pragma unroll
            for (int nf = 0; nf < 8; nf++) {
                mx0 = fmaxf(mx0, fmaxf(sfr[nf][0], sfr[nf][1]));
                mx1 = fmaxf(mx1, fmaxf(sfr[nf][2], sfr[nf][3]));
            }
            mx0 = fmaxf(mx0, __shfl_xor_sync(0xffffffffu, mx0, 1));
            mx0 = fmaxf(mx0, __shfl_xor_sync(0xffffffffu, mx0, 2));
            mx1 = fmaxf(mx1, __shfl_xor_sync(0xffffffffu, mx1, 1));
            mx1 = fmaxf(mx1, __shfl_xor_sync(0xffffffffu, mx1, 2));
            float mn0 = fmaxf(m0, mx0), mn1 = fmaxf(m1, mx1);
            float sc0 = __expf(m0 - mn0), sc1 = __expf(m1 - mn1);

            float sum0 = 0.f, sum1 = 0.f;
            uint32_t pa[4][4];
            #pragma unroll
            for (int nf = 0; nf < 8; nf++) {
                float p0 = __expf(sfr[nf][0] - mn0);
                float p1 = __expf(sfr[nf][1] - mn0);
                float p2 = __expf(sfr[nf][2] - mn1);
                float p3 = __expf(sfr[nf][3] - mn1);
                sum0 += p0 + p1;
                sum1 += p2 + p3;
                pa[nf >> 1][(nf & 1) * 2 + 0] = pack_hf2(p0, p1);
                pa[nf >> 1][(nf & 1) * 2 + 1] = pack_hf2(p2, p3);
            }
            sum0 += __shfl_xor_sync(0xffffffffu, sum0, 1);
            sum0 += __shfl_xor_sync(0xffffffffu, sum0, 2);
            sum1 += __shfl_xor_sync(0xffffffffu, sum1, 1);
            sum1 += __shfl_xor_sync(0xffffffffu, sum1, 2);
            l0 = l0 * sc0 + sum0;
            l1 = l1 * sc1 + sum1;
            m0 = mn0; m1 = mn1;

            // ---- rescale + PV ----
            #pragma unroll
            for (int i = 0; i < 32; i++) {
                acc[i][0] *= sc0; acc[i][1] *= sc0;
                acc[i][2] *= sc1; acc[i][3] *= sc1;
            }
            #pragma unroll
            for (int ks = 0; ks < 4; ks++) {
                #pragma unroll
                for (int g = 0; g < 16; g++) {
                    uint32_t vH[4];
                    uint32_t bo = ((ks * 16 + vbRow) * SV + g * 16 + vbCol) * 2;
                    ldmx4t(vH, vb + bo);
                    mma16816h(acc[g*2+0], pa[ks], vH);
                    mma16816h(acc[g*2+1], pa[ks], vH + 2);
                }
            }
        }

        // ---- normalize + store ----
        {
            float invl0 = 1.f / l0;
            float invl1 = 1.f / l1;
            int row0 = q0 + wid * 16 + r0l;
            int row1 = row0 + 8;
            #pragma unroll
            for (int nf = 0; nf < 32; nf++) {
                int cl = nf * 8 + cql;
                int g  = cl >> 6, d = cl & 63;
                size_t ob0 = ((size_t)(b * S_ + row0)) * HID_ + (g * HKV_ + h) * HD_ + d;
                size_t ob1 = ((size_t)(b * S_ + row1)) * HID_ + (g * HKV_ + h) * HD_ + d;
                *reinterpret_cast<float2*>(&Out[ob0]) =
                    make_float2(acc[nf][0] * invl0, acc[nf][1] * invl0);
                *reinterpret_cast<float2*>(&Out[ob1]) =
                    make_float2(acc[nf][2] * invl1, acc[nf][3] * invl1);
            }
        }
    }
}

// ---------------------------------------------------------------------------
extern "C" void kernel_launch(void* const* d_in, const int* in_sizes, int n_in,
                              void* d_out, int out_size) {
    const float* X   = (const float*)d_in[0];
    const int*   pid = (const int*)  d_in[1];
    const float* Wq  = (const float*)d_in[2];
    const float* Wk  = (const float*)d_in[3];
    const float* Wv  = (const float*)d_in[4];
    float* Out = (float*)d_out;

    uint4 *qh, *kh, *vh;
    cudaGetSymbolAddress((void**)&qh, g_Qh);
    cudaGetSymbolAddress((void**)&kh, g_Kh);
    cudaGetSymbolAddress((void**)&vh, g_Vh);
    uint2 *xh, *wqh, *wkh, *wvh;
    cudaGetSymbolAddress((void**)&xh,  g_Xh);
    cudaGetSymbolAddress((void**)&wqh, g_Wqh);
    cudaGetSymbolAddress((void**)&wkh, g_Wkh);
    cudaGetSymbolAddress((void**)&wvh, g_Wvh);

    // Fused pre-convert (2 float4 per thread)
    {
        int nX4 = M_ * HID_ / 4;
        dim3 grd((nX4 / 2 + 255) / 256, 4);
        cvt_all_kernel<<<grd, 256>>>((const float4*)X, (const float4*)Wq,
                                     (const float4*)Wk, (const float4*)Wv,
                                     xh, wqh, wkh, wvh);
    }
    // Fused projections + in-epilogue RoPE, CTA 128x128 occ-2
    {
        cudaFuncSetAttribute(gemm_fused_kernel,
                             cudaFuncAttributeMaxDynamicSharedMemorySize, GEMM_SMEM);
        dim3 grd(24, M_ / 128);
        gemm_fused_kernel<<<grd, 256, GEMM_SMEM>>>(
            (const char*)xh, (const char*)wqh, (__half*)qh,
            (const char*)wkh, (__half*)kh, (const char*)wvh, (__half*)vh, pid);
    }
    // Attention (FA2-style, paired scheduling, 4-stage K/V ring)
    {
        cudaFuncSetAttribute(attn_mma_kernel,
                             cudaFuncAttributeMaxDynamicSharedMemorySize, ATTN_SMEM);
        dim3 grd(NQT / 2, HKV_, B_);
        attn_mma_kernel<<<grd, 256, ATTN_SMEM>>>(qh, kh, vh, Out);
    }
}